// round 14
// baseline (speedup 1.0000x reference)
#include <cuda_runtime.h>
#include <cuda_bf16.h>
#include <math.h>
#include <stdint.h>

#define NB 8
#define NT 16
#define NL 128
#define NR 1024
#define NE 5
#define NF 512
#define RS (NE * NF)      // 2560

#define BRN 64            // r-tile per CTA (MMA N)
#define BKF 64            // fp32 K per chunk
#define NITER (NE * (NF / BKF))   // 40
#define NSTAGE 3
#define NTHR 1024

#if defined(__CUDA_ARCH__) && (defined(__CUDA_ARCH_FEAT_SM103_ALL) || defined(__CUDA_ARCH_FEAT_SM100_ALL))
#define HAS_TC 1
#else
#define HAS_TC 0
#endif

__device__ float g_part[NB * 16 * NT];   // [b][rtile][t]
__device__ unsigned int g_ctr;

// ---------------------------------------------------------------- helpers
__device__ __forceinline__ uint32_t smem_u32(const void* p) {
    uint32_t a;
    asm("{ .reg .u64 t; cvta.to.shared.u64 t, %1; cvt.u32.u64 %0, t; }" : "=r"(a) : "l"(p));
    return a;
}
__device__ __forceinline__ uint32_t packbf2(__nv_bfloat162 v) {
    return *reinterpret_cast<uint32_t*>(&v);
}

#if HAS_TC
#define MBAR_INIT(a, n) asm volatile("mbarrier.init.shared.b64 [%0], %1;" :: "r"(a), "r"(n) : "memory")
#define MBAR_WAIT(a, ph) do {                                                     \
    uint32_t _m = (a), _p = (ph), _d;                                             \
    asm volatile("{\n\t.reg .pred p;\n\t"                                         \
        "mbarrier.try_wait.parity.acquire.cta.shared::cta.b64 p, [%1], %2;\n\t"   \
        "selp.b32 %0, 1, 0, p;\n\t}" : "=r"(_d) : "r"(_m), "r"(_p) : "memory");   \
    if (!_d) {                                                                    \
        asm volatile("{\n\t.reg .pred P1;\n\tW%=:\n\t"                            \
            "mbarrier.try_wait.parity.acquire.cta.shared::cta.b64 P1, [%0], %1, 0x989680;\n\t" \
            "@P1 bra.uni D%=;\n\tbra.uni W%=;\n\tD%=:\n\t}"                       \
            :: "r"(_m), "r"(_p) : "memory");                                      \
    }                                                                             \
} while (0)
#define FENCE_ASYNC_SHARED() asm volatile("fence.proxy.async.shared::cta;" ::: "memory")
#define TC_ALLOC(sm_, n)  asm volatile("tcgen05.alloc.cta_group::1.sync.aligned.shared::cta.b32 [%0], %1;" :: "r"(sm_), "r"(n) : "memory")
#define TC_DEALLOC(t, n)  asm volatile("tcgen05.dealloc.cta_group::1.sync.aligned.b32 %0, %1;" :: "r"(t), "r"(n))
#define TC_RELINQ()       asm volatile("tcgen05.relinquish_alloc_permit.cta_group::1.sync.aligned;")
#define TC_COMMIT(mb)     asm volatile("tcgen05.commit.cta_group::1.mbarrier::arrive::one.shared::cluster.b64 [%0];" :: "r"(mb) : "memory")
#define TC_FENCE_AFTER()  asm volatile("tcgen05.fence::after_thread_sync;" ::: "memory")
#define TC_FENCE_BEFORE() asm volatile("tcgen05.fence::before_thread_sync;" ::: "memory")
#define TC_WAIT_LD()      asm volatile("tcgen05.wait::ld.sync.aligned;" ::: "memory")

#define TC_LD_X4(r, ta) \
    asm volatile("tcgen05.ld.sync.aligned.32x32b.x4.b32 {%0,%1,%2,%3}, [%4];" \
        : "=r"((r)[0]),"=r"((r)[1]),"=r"((r)[2]),"=r"((r)[3]) : "r"(ta))

__device__ __forceinline__ uint64_t make_desc(uint32_t addr) {
    const uint64_t base =
        (uint64_t(2) << 61) | (uint64_t(1) << 46) | (uint64_t(64) << 32) | (uint64_t(1) << 16);
    return base | ((uint64_t)(addr >> 4) & 0x3FFF);
}
__device__ __forceinline__ void mma_bf16_ss(uint32_t d, uint64_t ad, uint64_t bd,
                                            uint32_t idesc, uint32_t en) {
    asm volatile("{\n\t.reg .pred p;\n\tsetp.ne.u32 p, %4, 0;\n\t"
        "tcgen05.mma.cta_group::1.kind::f16 [%0], %1, %2, %3, {%5,%5,%5,%5}, p;\n\t}"
        :: "r"(d), "l"(ad), "l"(bd), "r"(idesc), "r"(en), "r"(0u) : "memory");
}
#define FMA2(d, a, b, c) asm("fma.rn.f32x2 %0, %1, %2, %3;" : "=l"(d) : "l"(a), "l"(b), "l"(c))
#define ADD2(d, a, b)    asm("add.rn.f32x2 %0, %1, %2;"     : "=l"(d) : "l"(a), "l"(b))
#define MUL2(d, a, b)    asm("mul.rn.f32x2 %0, %1, %2;"     : "=l"(d) : "l"(a), "l"(b))
#define PACK2(d, lo, hi)  asm("mov.b64 %0, {%1, %2};" : "=l"(d) : "r"(lo), "r"(hi))
#define UNPACK2(lo, hi, s) asm("mov.b64 {%0, %1}, %2;" : "=r"(lo), "=r"(hi) : "l"(s))
#endif  // HAS_TC

#define IDESC ((1u << 4) | (1u << 7) | (1u << 10) | ((BRN / 8) << 17) | ((128 / 16) << 24))

// SMEM layout — relative to in-kernel 1024-aligned base.
#define SM_TMEMP 0
#define SM_EMPTYB 48         // 3 x 8B
#define SM_DONE 80
#define SM_LAST 96
#define SROT_OFF 128
#define SQ_OFF 896
#define RED_OFF 1664          // 32*16 floats = 2048B -> ends 3712
#define STAGE0 4096
#define STAGE_BYTES 49152
#define AHI_OFF(s) (STAGE0 + (s) * STAGE_BYTES)
#define ALO_OFF(s) (AHI_OFF(s) + 16384)
#define BHI_OFF(s) (AHI_OFF(s) + 32768)
#define BLO_OFF(s) (AHI_OFF(s) + 40960)
#define FUSED_SMEM (STAGE0 + NSTAGE * STAGE_BYTES + 1024)   // 152576

__device__ __forceinline__ uint32_t swz(uint32_t off) { return off ^ ((off >> 3) & 0x70); }

// ---------------------------------------------------------------------------
// Fused kernel. grid = (16 rtiles, 8 b), 1024 threads (32 warps).
// ---------------------------------------------------------------------------
__global__ void __launch_bounds__(NTHR, 1) fused_energy(
    const float* __restrict__ lig_feat,
    const float* __restrict__ rec_feat,
    const float* __restrict__ lig_coord,
    const float* __restrict__ rec_coord,
    const float* __restrict__ pre_rot,
    const float* __restrict__ trans,
    const int* __restrict__ ligc,
    const int* __restrict__ recc,
    float* __restrict__ out) {
    extern __shared__ char smraw[];
    const uint32_t sbraw = smem_u32(smraw);
    const uint32_t sb = (sbraw + 1023u) & ~1023u;
    char* sm = smraw + (sb - sbraw);

    const int tid = threadIdx.x;
    const int b = blockIdx.y;
    const int rtile = blockIdx.x;
    const int r0 = rtile * BRN;

    float* s_rot = (float*)(sm + SROT_OFF);
    float* s_qx = (float*)(sm + SQ_OFF);
    float* s_qy = s_qx + 64;
    float* s_qz = s_qx + 128;
    float* s_red = (float*)(sm + RED_OFF);   // [32 warps][16]
    volatile int* s_last = (volatile int*)(sm + SM_LAST);

    // ---- Phase 0: QR (LAPACK convention) + neg rec coords
    if (tid < NT) {
        const int t = tid;
        const float* A0 = pre_rot + (b * NT + t) * 9;
        float a00 = A0[0], a01 = A0[1], a02 = A0[2];
        float a10 = A0[3], a11 = A0[4], a12 = A0[5];
        float a20 = A0[6], a21 = A0[7], a22 = A0[8];
        float v1 = 0.f, v2 = 0.f, tau0 = 0.f;
        float xn2 = a10 * a10 + a20 * a20;
        if (xn2 > 0.f) {
            float beta = -copysignf(sqrtf(a00 * a00 + xn2), a00);
            tau0 = (beta - a00) / beta;
            float inv = 1.f / (a00 - beta);
            v1 = a10 * inv; v2 = a20 * inv;
            float w1 = a01 + v1 * a11 + v2 * a21;
            a01 -= tau0 * w1; a11 -= tau0 * v1 * w1; a21 -= tau0 * v2 * w1;
            float w2 = a02 + v1 * a12 + v2 * a22;
            a02 -= tau0 * w2; a12 -= tau0 * v1 * w2; a22 -= tau0 * v2 * w2;
        }
        float u2 = 0.f, tau1 = 0.f;
        if (a21 != 0.f) {
            float beta1 = -copysignf(sqrtf(a11 * a11 + a21 * a21), a11);
            tau1 = (beta1 - a11) / beta1;
            u2 = a21 / (a11 - beta1);
        }
        float H0m[3][3] = {
            {1.f - tau0, -tau0 * v1, -tau0 * v2},
            {-tau0 * v1, 1.f - tau0 * v1 * v1, -tau0 * v1 * v2},
            {-tau0 * v2, -tau0 * v1 * v2, 1.f - tau0 * v2 * v2}};
        float H1m[3][3] = {
            {1.f, 0.f, 0.f},
            {0.f, 1.f - tau1, -tau1 * u2},
            {0.f, -tau1 * u2, 1.f - tau1 * u2 * u2}};
#pragma unroll
        for (int i = 0; i < 3; i++)
#pragma unroll
            for (int jj = 0; jj < 3; jj++)
                s_rot[t * 12 + i * 3 + jj] =
                    H0m[i][0] * H1m[0][jj] + H0m[i][1] * H1m[1][jj] + H0m[i][2] * H1m[2][jj];
        s_rot[t * 12 + 9]  = trans[(b * NT + t) * 3 + 0];
        s_rot[t * 12 + 10] = trans[(b * NT + t) * 3 + 1];
        s_rot[t * 12 + 11] = trans[(b * NT + t) * 3 + 2];
    }
    if (tid >= 64 && tid < 128) {
        int r = r0 + (tid - 64);
        s_qx[tid - 64] = -rec_coord[((size_t)b * NR + r) * 3 + 0];
        s_qy[tid - 64] = -rec_coord[((size_t)b * NR + r) * 3 + 1];
        s_qz[tid - 64] = -rec_coord[((size_t)b * NR + r) * 3 + 2];
    }

    const int lc = __ldg(&ligc[b]);
    const int rc = __ldg(&recc[b]);
    const int lane = tid & 31;
    const int w = tid >> 5;

#if HAS_TC
    if (tid == 0) {
#pragma unroll
        for (int s = 0; s < NSTAGE; s++) MBAR_INIT(sb + SM_EMPTYB + 8 * s, 1);
        MBAR_INIT(sb + SM_DONE, 1);
    }
    if (w == 0) {
        TC_ALLOC(sb + SM_TMEMP, 512);
        TC_RELINQ();
    }
    __syncthreads();
    uint32_t tmem;
    asm volatile("ld.shared.b32 %0, [%1];" : "=r"(tmem) : "r"(sb + SM_TMEMP));

    const float* Abase = lig_feat + (size_t)b * NL * RS;
    const float* Bbase = rec_feat + ((size_t)b * NR + r0) * RS;

    // per-thread offsets: A rows (tid>>4)+64i for i=0,1; B row tid>>4 (0..63)
    size_t aoff[2];
    uint32_t soA[2];
#pragma unroll
    for (int i = 0; i < 2; i++) {
        int row = (tid >> 4) + 64 * i;
        aoff[i] = (size_t)row * RS + ((tid & 15) << 2);
        soA[i] = swz((uint32_t)row * 128 + ((tid & 15) << 3));
    }

    float4 pa0[2], pa1[2];
    float4 pb0, pb1;
    {
#pragma unroll
        for (int i = 0; i < 2; i++) pa0[i] = *(const float4*)(Abase + aoff[i]);
        pb0 = *(const float4*)(Bbase + aoff[0]);
    }

#define CVT_PAIR(V, HDST, LDST, SO)                                               \
    do {                                                                          \
        float4 v = (V);                                                           \
        __nv_bfloat162 h01 = __floats2bfloat162_rn(v.x, v.y);                     \
        __nv_bfloat162 h23 = __floats2bfloat162_rn(v.z, v.w);                     \
        float2 f01 = __bfloat1622float2(h01);                                     \
        float2 f23 = __bfloat1622float2(h23);                                     \
        __nv_bfloat162 l01 = __floats2bfloat162_rn(v.x - f01.x, v.y - f01.y);     \
        __nv_bfloat162 l23 = __floats2bfloat162_rn(v.z - f23.x, v.w - f23.y);     \
        *(uint2*)((HDST) + (SO)) = make_uint2(packbf2(h01), packbf2(h23));        \
        *(uint2*)((LDST) + (SO)) = make_uint2(packbf2(l01), packbf2(l23));        \
    } while (0)

#define STEP(ITER, CA, CB, NA, NB_)                                               \
    {                                                                             \
        const int iter_ = (ITER);                                                 \
        if (iter_ + 1 < NITER) {                                                  \
            const int nx = iter_ + 1;                                             \
            const float* An = Abase + (nx >> 3) * NF + (nx & 7) * BKF;            \
            const float* Bn = Bbase + (nx >> 3) * NF + (nx & 7) * BKF;            \
            _Pragma("unroll")                                                     \
            for (int i = 0; i < 2; i++) NA[i] = *(const float4*)(An + aoff[i]);   \
            NB_ = *(const float4*)(Bn + aoff[0]);                                 \
        }                                                                         \
        const int k_ = iter_ / 3;                                                 \
        const int s_ = iter_ - 3 * k_;                                            \
        MBAR_WAIT(sb + SM_EMPTYB + 8 * s_, (k_ & 1) ^ 1);                         \
        char* ah_ = sm + AHI_OFF(s_);                                             \
        char* al_ = sm + ALO_OFF(s_);                                             \
        _Pragma("unroll")                                                         \
        for (int i = 0; i < 2; i++) CVT_PAIR(CA[i], ah_, al_, soA[i]);            \
        CVT_PAIR(CB, sm + BHI_OFF(s_), sm + BLO_OFF(s_), soA[0]);                 \
        __syncthreads();                                                          \
        if (tid == 0) {                                                           \
            FENCE_ASYNC_SHARED();                                                 \
            uint64_t dah = make_desc(sb + AHI_OFF(s_));                           \
            uint64_t dal = make_desc(sb + ALO_OFF(s_));                           \
            uint64_t dbh = make_desc(sb + BHI_OFF(s_));                           \
            uint64_t dbl = make_desc(sb + BLO_OFF(s_));                           \
            uint32_t dcol = tmem + (iter_ >> 3) * 64;                             \
            const int kc_ = iter_ & 7;                                            \
            _Pragma("unroll")                                                     \
            for (int ks = 0; ks < 4; ks++) {                                      \
                uint64_t o = ks * 2;                                              \
                mma_bf16_ss(dcol, dah + o, dbh + o, IDESC, !(kc_ == 0 && ks == 0)); \
                mma_bf16_ss(dcol, dah + o, dbl + o, IDESC, 1u);                   \
                mma_bf16_ss(dcol, dal + o, dbh + o, IDESC, 1u);                   \
            }                                                                     \
            TC_COMMIT(sb + SM_EMPTYB + 8 * s_);                                   \
        }                                                                         \
    }

    for (int it2 = 0; it2 < NITER; it2 += 2) {
        STEP(it2, pa0, pb0, pa1, pb1);
        STEP(it2 + 1, pa1, pb1, pa0, pb0);
    }
#undef STEP
#undef CVT_PAIR

    if (tid == 0) TC_COMMIT(sb + SM_DONE);
    MBAR_WAIT(sb + SM_DONE, 0);
    TC_FENCE_AFTER();

    // ---- Phase 2: epilogue. 32 warps: warp w -> l rows (w&3)*32+lane,
    //      cols (w>>2)*8 .. +7 (two cchunks of 4).
    const int l = (w & 3) * 32 + lane;
    const int cg = w >> 2;             // 0..7
    const bool lok = l < lc;
    const float xl = lig_coord[((size_t)b * NL + l) * 3 + 0];
    const float yl = lig_coord[((size_t)b * NL + l) * 3 + 1];
    const float zl = lig_coord[((size_t)b * NL + l) * 3 + 2];

    uint64_t eps2;
    PACK2(eps2, __float_as_uint(1e-12f), __float_as_uint(1e-12f));

#pragma unroll
    for (int tp = 0; tp < 2; tp++) {        // two t-passes of 8
        uint64_t acc2[8];
#pragma unroll
        for (int t = 0; t < 8; t++) acc2[t] = 0ull;
#pragma unroll
        for (int cc = 0; cc < 2; cc++) {
            const int colbase = cg * 8 + cc * 4;
            uint64_t A2[NE][2];
            {
                uint32_t ar[NE][4];
#pragma unroll
                for (int e = 0; e < NE; e++)
                    TC_LD_X4(ar[e], tmem + e * 64 + colbase);
                TC_WAIT_LD();
                const int rgbase = r0 + colbase;
#pragma unroll
                for (int e = 0; e < NE; e++)
#pragma unroll
                    for (int j = 0; j < 2; j++) {
                        uint32_t v0 = (lok && (rgbase + 2 * j)     < rc) ? ar[e][2 * j]     : 0u;
                        uint32_t v1 = (lok && (rgbase + 2 * j + 1) < rc) ? ar[e][2 * j + 1] : 0u;
                        PACK2(A2[e][j], v0, v1);
                    }
            }
            const uint64_t* nqx = (const uint64_t*)(s_qx + colbase);
            const uint64_t* nqy = (const uint64_t*)(s_qy + colbase);
            const uint64_t* nqz = (const uint64_t*)(s_qz + colbase);
#pragma unroll
            for (int tt = 0; tt < 8; tt++) {
                const int t = tp * 8 + tt;
                const float* Rt = s_rot + t * 12;
                float px = fmaf(Rt[0], xl, fmaf(Rt[1], yl, fmaf(Rt[2], zl, Rt[9])));
                float py = fmaf(Rt[3], xl, fmaf(Rt[4], yl, fmaf(Rt[5], zl, Rt[10])));
                float pz = fmaf(Rt[6], xl, fmaf(Rt[7], yl, fmaf(Rt[8], zl, Rt[11])));
                uint64_t px2, py2, pz2;
                PACK2(px2, __float_as_uint(px), __float_as_uint(px));
                PACK2(py2, __float_as_uint(py), __float_as_uint(py));
                PACK2(pz2, __float_as_uint(pz), __float_as_uint(pz));
                uint64_t a = acc2[tt];
#pragma unroll
                for (int j = 0; j < 2; j++) {
                    uint64_t dx, dy, dz, d2, t1, t2;
                    ADD2(dx, px2, nqx[j]);
                    ADD2(dy, py2, nqy[j]);
                    ADD2(dz, pz2, nqz[j]);
                    FMA2(t1, dz, dz, eps2);
                    FMA2(t2, dy, dy, t1);
                    FMA2(d2, dx, dx, t2);
                    uint32_t lo, hi;
                    UNPACK2(lo, hi, d2);
                    float ia = rsqrtf(__uint_as_float(lo));
                    float ib = rsqrtf(__uint_as_float(hi));
                    uint64_t inv, inv2, inv3, dd;
                    PACK2(inv, __float_as_uint(ia), __float_as_uint(ib));
                    MUL2(inv2, inv, inv);
                    MUL2(inv3, inv2, inv);
                    MUL2(dd, d2, inv);
                    FMA2(a, A2[0][j], inv3, a);
                    FMA2(a, A2[1][j], inv2, a);
                    FMA2(a, A2[2][j], inv, a);
                    FMA2(a, A2[3][j], dd, a);
                    FMA2(a, A2[4][j], d2, a);
                }
                acc2[tt] = a;
            }
        }
        // reduce this t-pass across the warp, accumulate into s_red[w][t]
#pragma unroll
        for (int tt = 0; tt < 8; tt++) {
            uint32_t lo, hi;
            UNPACK2(lo, hi, acc2[tt]);
            float v = __uint_as_float(lo) + __uint_as_float(hi);
#pragma unroll
            for (int off = 16; off > 0; off >>= 1)
                v += __shfl_xor_sync(0xffffffffu, v, off);
            if (lane == 0) {
                int t = tp * 8 + tt;
                if (tp == 0) s_red[w * NT + t] = v;
                else         s_red[w * NT + t] = s_red[w * NT + t] * 0.f + v;  // distinct slots per tp half
            }
        }
    }
    TC_FENCE_BEFORE();
    __syncthreads();
    if (w == 0) TC_DEALLOC(tmem, 512);

#else  // ------------------------- SIMT fallback (non-'a' pass) -------------
    __syncthreads();
    const int g = tid >> 4;          // 0..63 -> r index
    const int j16 = tid & 15;
    const int r = r0 + g;
    const bool rok = r < rc;
    const float qx = rec_coord[((size_t)b * NR + r) * 3 + 0];
    const float qy = rec_coord[((size_t)b * NR + r) * 3 + 1];
    const float qz = rec_coord[((size_t)b * NR + r) * 3 + 2];
    float accs = 0.f;                // this thread's single t = j16
    const int tmine = j16;

    for (int l = 0; l < NL; l++) {
        float dot[NE];
#pragma unroll
        for (int e = 0; e < NE; e++) dot[e] = 0.f;
        if (l < lc && rok) {
            const float* Arow = lig_feat + ((size_t)b * NL + l) * RS;
            const float* Brow = rec_feat + ((size_t)b * NR + r) * RS;
#pragma unroll
            for (int e = 0; e < NE; e++) {
                float sacc = 0.f;
                for (int f = j16 * 4; f < NF; f += 64) {
                    float4 av = *(const float4*)(Arow + e * NF + f);
                    float4 bv = *(const float4*)(Brow + e * NF + f);
                    sacc += av.x * bv.x + av.y * bv.y + av.z * bv.z + av.w * bv.w;
                }
                dot[e] = sacc;
            }
        }
#pragma unroll
        for (int e = 0; e < NE; e++) {
            dot[e] += __shfl_xor_sync(0xffffffffu, dot[e], 1);
            dot[e] += __shfl_xor_sync(0xffffffffu, dot[e], 2);
            dot[e] += __shfl_xor_sync(0xffffffffu, dot[e], 4);
            dot[e] += __shfl_xor_sync(0xffffffffu, dot[e], 8);
        }
        float xl = lig_coord[((size_t)b * NL + l) * 3 + 0];
        float yl = lig_coord[((size_t)b * NL + l) * 3 + 1];
        float zl = lig_coord[((size_t)b * NL + l) * 3 + 2];
        {
            const float* Rt = s_rot + tmine * 12;
            float px = fmaf(Rt[0], xl, fmaf(Rt[1], yl, fmaf(Rt[2], zl, Rt[9])));
            float py = fmaf(Rt[3], xl, fmaf(Rt[4], yl, fmaf(Rt[5], zl, Rt[10])));
            float pz = fmaf(Rt[6], xl, fmaf(Rt[7], yl, fmaf(Rt[8], zl, Rt[11])));
            float dx = px - qx, dy = py - qy, dz = pz - qz;
            float d2 = fmaf(dx, dx, fmaf(dy, dy, dz * dz));
            d2 = fmaxf(d2, 1e-12f);
            float inv = rsqrtf(d2);
            float inv2 = inv * inv;
            float inv3 = inv2 * inv;
            float d = d2 * inv;
            accs += fmaf(dot[0], inv3, fmaf(dot[1], inv2,
                        fmaf(dot[2], inv, fmaf(dot[3], d, dot[4] * d2))));
        }
    }
    // accumulate: each warp covers 2 r values x 16 t. s_red[w][t] gets both halves.
    {
        float other = __shfl_xor_sync(0xffffffffu, accs, 16);
        if (lane < 16) s_red[w * NT + tmine] = accs + other;
    }
#endif

    __syncthreads();
    // final cross-warp reduction: thread t<16 sums s_red over 32 warps
    if (tid < NT) {
        float s = 0.f;
#pragma unroll
        for (int ww = 0; ww < 32; ww++) s += s_red[ww * NT + tid];
        __stcg(&g_part[(b * 16 + rtile) * NT + tid], s);
    }
    __threadfence();
    __syncthreads();

    if (tid == 0) {
        unsigned old = atomicAdd(&g_ctr, 1u);
        *s_last = ((old & 127u) == 127u) ? 1 : 0;   // grid = 128 CTAs
    }
    __syncthreads();
    if (*s_last) {
        __threadfence();
        if (tid < NB * NT) {
            int bb = tid >> 4, t = tid & 15;
            float ssum = 0.f;
#pragma unroll
            for (int rt = 0; rt < 16; rt++)
                ssum += __ldcg(&g_part[(bb * 16 + rt) * NT + t]);
            out[bb * NT + t] = ssum;
        }
    }
}

// ---------------------------------------------------------------------------
extern "C" void kernel_launch(void* const* d_in, const int* in_sizes, int n_in,
                              void* d_out, int out_size) {
    (void)in_sizes; (void)n_in; (void)out_size;
    const float* lig_feat   = (const float*)d_in[0];
    const float* rec_feat   = (const float*)d_in[1];
    const float* lig_coord  = (const float*)d_in[2];
    const float* rec_coord  = (const float*)d_in[3];
    const float* pre_rot    = (const float*)d_in[4];
    const float* trans      = (const float*)d_in[5];
    const int*   lig_counts = (const int*)d_in[6];
    const int*   rec_counts = (const int*)d_in[7];
    float* out = (float*)d_out;

    cudaFuncSetAttribute(fused_energy, cudaFuncAttributeMaxDynamicSharedMemorySize, FUSED_SMEM);

    dim3 g1(16, NB);
    fused_energy<<<g1, NTHR, FUSED_SMEM>>>(lig_feat, rec_feat, lig_coord, rec_coord,
                                           pre_rot, trans, lig_counts, rec_counts, out);
}

// round 15
// speedup vs baseline: 1.0618x; 1.0618x over previous
#include <cuda_runtime.h>
#include <cuda_bf16.h>
#include <math.h>
#include <stdint.h>

#define NB 8
#define NT 16
#define NL 128
#define NR 1024
#define NE 5
#define NF 512
#define RS (NE * NF)      // 2560

#define BRN 64            // r-tile per CTA (MMA N)
#define BKF 64            // fp32 K per chunk
#define NITER (NE * (NF / BKF))   // 40
#define NSTAGE 3
#define NCVT 512          // producer threads (16 warps)
#define NTHR 544          // + 1 MMA warp

#if defined(__CUDA_ARCH__) && (defined(__CUDA_ARCH_FEAT_SM103_ALL) || defined(__CUDA_ARCH_FEAT_SM100_ALL))
#define HAS_TC 1
#else
#define HAS_TC 0
#endif

__device__ float g_part[NB * 16 * NT];   // [b][rtile][t]
__device__ unsigned int g_ctr;

// ---------------------------------------------------------------- helpers
__device__ __forceinline__ uint32_t smem_u32(const void* p) {
    uint32_t a;
    asm("{ .reg .u64 t; cvta.to.shared.u64 t, %1; cvt.u32.u64 %0, t; }" : "=r"(a) : "l"(p));
    return a;
}
__device__ __forceinline__ uint32_t packbf2(__nv_bfloat162 v) {
    return *reinterpret_cast<uint32_t*>(&v);
}

#if HAS_TC
#define MBAR_INIT(a, n) asm volatile("mbarrier.init.shared.b64 [%0], %1;" :: "r"(a), "r"(n) : "memory")
#define MBAR_ARRIVE(a)  asm volatile("mbarrier.arrive.release.cta.shared::cta.b64 _, [%0];" :: "r"(a) : "memory")
#define MBAR_WAIT(a, ph) do {                                                     \
    uint32_t _m = (a), _p = (ph), _d;                                             \
    asm volatile("{\n\t.reg .pred p;\n\t"                                         \
        "mbarrier.try_wait.parity.acquire.cta.shared::cta.b64 p, [%1], %2;\n\t"   \
        "selp.b32 %0, 1, 0, p;\n\t}" : "=r"(_d) : "r"(_m), "r"(_p) : "memory");   \
    if (!_d) {                                                                    \
        asm volatile("{\n\t.reg .pred P1;\n\tW%=:\n\t"                            \
            "mbarrier.try_wait.parity.acquire.cta.shared::cta.b64 P1, [%0], %1, 0x989680;\n\t" \
            "@P1 bra.uni D%=;\n\tbra.uni W%=;\n\tD%=:\n\t}"                       \
            :: "r"(_m), "r"(_p) : "memory");                                      \
    }                                                                             \
} while (0)
#define FENCE_ASYNC_SHARED() asm volatile("fence.proxy.async.shared::cta;" ::: "memory")
#define BAR_SYNC(id, n)   asm volatile("bar.sync %0, %1;" :: "r"(id), "r"(n) : "memory")
#define TC_ALLOC(sm_, n)  asm volatile("tcgen05.alloc.cta_group::1.sync.aligned.shared::cta.b32 [%0], %1;" :: "r"(sm_), "r"(n) : "memory")
#define TC_DEALLOC(t, n)  asm volatile("tcgen05.dealloc.cta_group::1.sync.aligned.b32 %0, %1;" :: "r"(t), "r"(n))
#define TC_RELINQ()       asm volatile("tcgen05.relinquish_alloc_permit.cta_group::1.sync.aligned;")
#define TC_COMMIT(mb)     asm volatile("tcgen05.commit.cta_group::1.mbarrier::arrive::one.shared::cluster.b64 [%0];" :: "r"(mb) : "memory")
#define TC_FENCE_AFTER()  asm volatile("tcgen05.fence::after_thread_sync;" ::: "memory")
#define TC_FENCE_BEFORE() asm volatile("tcgen05.fence::before_thread_sync;" ::: "memory")
#define TC_WAIT_LD()      asm volatile("tcgen05.wait::ld.sync.aligned;" ::: "memory")

#define TC_LD_X8(r, ta) \
    asm volatile("tcgen05.ld.sync.aligned.32x32b.x8.b32 " \
        "{%0,%1,%2,%3,%4,%5,%6,%7}, [%8];" \
        : "=r"((r)[0]),"=r"((r)[1]),"=r"((r)[2]),"=r"((r)[3]), \
          "=r"((r)[4]),"=r"((r)[5]),"=r"((r)[6]),"=r"((r)[7]) \
        : "r"(ta))

__device__ __forceinline__ uint64_t make_desc(uint32_t addr) {
    const uint64_t base =
        (uint64_t(2) << 61) | (uint64_t(1) << 46) | (uint64_t(64) << 32) | (uint64_t(1) << 16);
    return base | ((uint64_t)(addr >> 4) & 0x3FFF);
}
__device__ __forceinline__ void mma_bf16_ss(uint32_t d, uint64_t ad, uint64_t bd,
                                            uint32_t idesc, uint32_t en) {
    asm volatile("{\n\t.reg .pred p;\n\tsetp.ne.u32 p, %4, 0;\n\t"
        "tcgen05.mma.cta_group::1.kind::f16 [%0], %1, %2, %3, {%5,%5,%5,%5}, p;\n\t}"
        :: "r"(d), "l"(ad), "l"(bd), "r"(idesc), "r"(en), "r"(0u) : "memory");
}
#define FMA2(d, a, b, c) asm("fma.rn.f32x2 %0, %1, %2, %3;" : "=l"(d) : "l"(a), "l"(b), "l"(c))
#define ADD2(d, a, b)    asm("add.rn.f32x2 %0, %1, %2;"     : "=l"(d) : "l"(a), "l"(b))
#define MUL2(d, a, b)    asm("mul.rn.f32x2 %0, %1, %2;"     : "=l"(d) : "l"(a), "l"(b))
#define PACK2(d, lo, hi)  asm("mov.b64 %0, {%1, %2};" : "=l"(d) : "r"(lo), "r"(hi))
#define UNPACK2(lo, hi, s) asm("mov.b64 {%0, %1}, %2;" : "=r"(lo), "=r"(hi) : "l"(s))
#endif  // HAS_TC

#define IDESC ((1u << 4) | (1u << 7) | (1u << 10) | ((BRN / 8) << 17) | ((128 / 16) << 24))

// SMEM layout — relative to in-kernel 1024-aligned base.
#define SM_TMEMP 0
#define SM_FULLB 16          // 3 x 8B, arrive count 1 (tid0 after producer bar)
#define SM_EMPTYB 48         // 3 x 8B, arrive count 1 (tcgen05 commit)
#define SM_DONE 80
#define SM_LAST 96
#define SROT_OFF 128
#define SQ_OFF 896
#define RED_OFF 1664
#define STAGE0 3072
#define STAGE_BYTES 49152
#define AHI_OFF(s) (STAGE0 + (s) * STAGE_BYTES)
#define ALO_OFF(s) (AHI_OFF(s) + 16384)
#define BHI_OFF(s) (AHI_OFF(s) + 32768)
#define BLO_OFF(s) (AHI_OFF(s) + 40960)
#define FUSED_SMEM (STAGE0 + NSTAGE * STAGE_BYTES + 1024)

__device__ __forceinline__ uint32_t swz(uint32_t off) { return off ^ ((off >> 3) & 0x70); }

// ---------------------------------------------------------------------------
// Fused kernel. grid = (16 rtiles, 8 b), 544 threads (16 producer warps + 1 MMA warp).
// ---------------------------------------------------------------------------
__global__ void __launch_bounds__(NTHR, 1) fused_energy(
    const float* __restrict__ lig_feat,
    const float* __restrict__ rec_feat,
    const float* __restrict__ lig_coord,
    const float* __restrict__ rec_coord,
    const float* __restrict__ pre_rot,
    const float* __restrict__ trans,
    const int* __restrict__ ligc,
    const int* __restrict__ recc,
    float* __restrict__ out) {
    extern __shared__ char smraw[];
    const uint32_t sbraw = smem_u32(smraw);
    const uint32_t sb = (sbraw + 1023u) & ~1023u;
    char* sm = smraw + (sb - sbraw);

    const int tid = threadIdx.x;
    const int b = blockIdx.y;
    const int rtile = blockIdx.x;
    const int r0 = rtile * BRN;

    float* s_rot = (float*)(sm + SROT_OFF);
    float* s_qx = (float*)(sm + SQ_OFF);
    float* s_qy = s_qx + 64;
    float* s_qz = s_qx + 128;
    float* s_red = (float*)(sm + RED_OFF);
    volatile int* s_last = (volatile int*)(sm + SM_LAST);

    // ---- Phase 0: QR (LAPACK convention) + neg rec coords
    if (tid < NT) {
        const int t = tid;
        const float* A0 = pre_rot + (b * NT + t) * 9;
        float a00 = A0[0], a01 = A0[1], a02 = A0[2];
        float a10 = A0[3], a11 = A0[4], a12 = A0[5];
        float a20 = A0[6], a21 = A0[7], a22 = A0[8];
        float v1 = 0.f, v2 = 0.f, tau0 = 0.f;
        float xn2 = a10 * a10 + a20 * a20;
        if (xn2 > 0.f) {
            float beta = -copysignf(sqrtf(a00 * a00 + xn2), a00);
            tau0 = (beta - a00) / beta;
            float inv = 1.f / (a00 - beta);
            v1 = a10 * inv; v2 = a20 * inv;
            float w1 = a01 + v1 * a11 + v2 * a21;
            a01 -= tau0 * w1; a11 -= tau0 * v1 * w1; a21 -= tau0 * v2 * w1;
            float w2 = a02 + v1 * a12 + v2 * a22;
            a02 -= tau0 * w2; a12 -= tau0 * v1 * w2; a22 -= tau0 * v2 * w2;
        }
        float u2 = 0.f, tau1 = 0.f;
        if (a21 != 0.f) {
            float beta1 = -copysignf(sqrtf(a11 * a11 + a21 * a21), a11);
            tau1 = (beta1 - a11) / beta1;
            u2 = a21 / (a11 - beta1);
        }
        float H0m[3][3] = {
            {1.f - tau0, -tau0 * v1, -tau0 * v2},
            {-tau0 * v1, 1.f - tau0 * v1 * v1, -tau0 * v1 * v2},
            {-tau0 * v2, -tau0 * v1 * v2, 1.f - tau0 * v2 * v2}};
        float H1m[3][3] = {
            {1.f, 0.f, 0.f},
            {0.f, 1.f - tau1, -tau1 * u2},
            {0.f, -tau1 * u2, 1.f - tau1 * u2 * u2}};
#pragma unroll
        for (int i = 0; i < 3; i++)
#pragma unroll
            for (int jj = 0; jj < 3; jj++)
                s_rot[t * 12 + i * 3 + jj] =
                    H0m[i][0] * H1m[0][jj] + H0m[i][1] * H1m[1][jj] + H0m[i][2] * H1m[2][jj];
        s_rot[t * 12 + 9]  = trans[(b * NT + t) * 3 + 0];
        s_rot[t * 12 + 10] = trans[(b * NT + t) * 3 + 1];
        s_rot[t * 12 + 11] = trans[(b * NT + t) * 3 + 2];
    }
    if (tid >= 64 && tid < 128) {
        int r = r0 + (tid - 64);
        s_qx[tid - 64] = -rec_coord[((size_t)b * NR + r) * 3 + 0];
        s_qy[tid - 64] = -rec_coord[((size_t)b * NR + r) * 3 + 1];
        s_qz[tid - 64] = -rec_coord[((size_t)b * NR + r) * 3 + 2];
    }

    const int lc = __ldg(&ligc[b]);
    const int rc = __ldg(&recc[b]);
    const int lane = tid & 31;
    const int w = tid >> 5;

#if HAS_TC
    if (tid == 0) {
#pragma unroll
        for (int s = 0; s < NSTAGE; s++) {
            MBAR_INIT(sb + SM_FULLB + 8 * s, 1);
            MBAR_INIT(sb + SM_EMPTYB + 8 * s, 1);
        }
        MBAR_INIT(sb + SM_DONE, 1);
    }
    if (w == 0) {
        TC_ALLOC(sb + SM_TMEMP, 512);
        TC_RELINQ();
    }
    __syncthreads();
    uint32_t tmem;
    asm volatile("ld.shared.b32 %0, [%1];" : "=r"(tmem) : "r"(sb + SM_TMEMP));

    if (tid < NCVT) {
        // =================== producer warps (0..15) ===================
        const float* Abase = lig_feat + (size_t)b * NL * RS;
        const float* Bbase = rec_feat + ((size_t)b * NR + r0) * RS;

        size_t aoff[4];
        uint32_t soA[4];
#pragma unroll
        for (int i = 0; i < 4; i++) {
            int row = (tid >> 4) + 32 * i;
            aoff[i] = (size_t)row * RS + ((tid & 15) << 2);
            soA[i] = swz((uint32_t)row * 128 + ((tid & 15) << 3));
        }

        float4 pa0[4], pb0[2], pa1[4], pb1[2];
        {
#pragma unroll
            for (int i = 0; i < 4; i++) pa0[i] = *(const float4*)(Abase + aoff[i]);
#pragma unroll
            for (int i = 0; i < 2; i++) pb0[i] = *(const float4*)(Bbase + aoff[i]);
        }

#define CVT_PAIR(V, HDST, LDST, SO)                                               \
    do {                                                                          \
        float4 v = (V);                                                           \
        __nv_bfloat162 h01 = __floats2bfloat162_rn(v.x, v.y);                     \
        __nv_bfloat162 h23 = __floats2bfloat162_rn(v.z, v.w);                     \
        float2 f01 = __bfloat1622float2(h01);                                     \
        float2 f23 = __bfloat1622float2(h23);                                     \
        __nv_bfloat162 l01 = __floats2bfloat162_rn(v.x - f01.x, v.y - f01.y);     \
        __nv_bfloat162 l23 = __floats2bfloat162_rn(v.z - f23.x, v.w - f23.y);     \
        *(uint2*)((HDST) + (SO)) = make_uint2(packbf2(h01), packbf2(h23));        \
        *(uint2*)((LDST) + (SO)) = make_uint2(packbf2(l01), packbf2(l23));        \
    } while (0)

#define STEP(ITER, CA, CB, NA, NB_)                                               \
    {                                                                             \
        const int iter_ = (ITER);                                                 \
        if (iter_ + 1 < NITER) {                                                  \
            const int nx = iter_ + 1;                                             \
            const float* An = Abase + (nx >> 3) * NF + (nx & 7) * BKF;            \
            const float* Bn = Bbase + (nx >> 3) * NF + (nx & 7) * BKF;            \
            _Pragma("unroll")                                                     \
            for (int i = 0; i < 4; i++) NA[i] = *(const float4*)(An + aoff[i]);   \
            _Pragma("unroll")                                                     \
            for (int i = 0; i < 2; i++) NB_[i] = *(const float4*)(Bn + aoff[i]);  \
        }                                                                         \
        const int k_ = iter_ / 3;                                                 \
        const int s_ = iter_ - 3 * k_;                                            \
        MBAR_WAIT(sb + SM_EMPTYB + 8 * s_, (k_ & 1) ^ 1);                         \
        char* ah_ = sm + AHI_OFF(s_);                                             \
        char* al_ = sm + ALO_OFF(s_);                                             \
        _Pragma("unroll")                                                         \
        for (int i = 0; i < 4; i++) CVT_PAIR(CA[i], ah_, al_, soA[i]);            \
        char* bh_ = sm + BHI_OFF(s_);                                             \
        char* bl_ = sm + BLO_OFF(s_);                                             \
        _Pragma("unroll")                                                         \
        for (int i = 0; i < 2; i++) CVT_PAIR(CB[i], bh_, bl_, soA[i]);            \
        BAR_SYNC(1, NCVT);                                                        \
        if (tid == 0) MBAR_ARRIVE(sb + SM_FULLB + 8 * s_);                        \
    }

        for (int it2 = 0; it2 < NITER; it2 += 2) {
            STEP(it2, pa0, pb0, pa1, pb1);
            STEP(it2 + 1, pa1, pb1, pa0, pb0);
        }
#undef STEP
#undef CVT_PAIR
    } else if (tid == NCVT) {
        // =================== MMA warp (warp 16, one thread) ===================
        for (int iter = 0; iter < NITER; iter++) {
            const int k = iter / 3;
            const int s = iter - 3 * k;
            MBAR_WAIT(sb + SM_FULLB + 8 * s, k & 1);
            FENCE_ASYNC_SHARED();
            uint64_t dah = make_desc(sb + AHI_OFF(s));
            uint64_t dal = make_desc(sb + ALO_OFF(s));
            uint64_t dbh = make_desc(sb + BHI_OFF(s));
            uint64_t dbl = make_desc(sb + BLO_OFF(s));
            uint32_t dcol = tmem + (iter >> 3) * 64;
            const int kc = iter & 7;
#pragma unroll
            for (int ks = 0; ks < 4; ks++) {
                uint64_t o = ks * 2;
                mma_bf16_ss(dcol, dah + o, dbh + o, IDESC, !(kc == 0 && ks == 0));
                mma_bf16_ss(dcol, dah + o, dbl + o, IDESC, 1u);
                mma_bf16_ss(dcol, dal + o, dbh + o, IDESC, 1u);
            }
            TC_COMMIT(sb + SM_EMPTYB + 8 * s);
        }
        TC_COMMIT(sb + SM_DONE);
    }

    MBAR_WAIT(sb + SM_DONE, 0);
    TC_FENCE_AFTER();

    // ---- Phase 2: epilogue (warps 0..15; warp 16 passes through)
    float accf[NT];
    if (w < 16) {
        const int l = (w & 3) * 32 + lane;
        const int colq = w >> 2;
        const bool lok = l < lc;
        const float xl = lig_coord[((size_t)b * NL + l) * 3 + 0];
        const float yl = lig_coord[((size_t)b * NL + l) * 3 + 1];
        const float zl = lig_coord[((size_t)b * NL + l) * 3 + 2];

        uint64_t eps2;
        PACK2(eps2, __float_as_uint(1e-12f), __float_as_uint(1e-12f));

#pragma unroll
        for (int tp = 0; tp < 2; tp++) {
            uint64_t acc2[8];
#pragma unroll
            for (int t = 0; t < 8; t++) acc2[t] = 0ull;
#pragma unroll
            for (int cchunk = 0; cchunk < 2; cchunk++) {
                const int colbase = colq * 16 + cchunk * 8;
                uint64_t A2[NE][4];
                {
                    uint32_t ar[NE][8];
#pragma unroll
                    for (int e = 0; e < NE; e++)
                        TC_LD_X8(ar[e], tmem + e * 64 + colbase);
                    TC_WAIT_LD();
                    const int rgbase = r0 + colbase;
#pragma unroll
                    for (int e = 0; e < NE; e++)
#pragma unroll
                        for (int j = 0; j < 4; j++) {
                            uint32_t v0 = (lok && (rgbase + 2 * j)     < rc) ? ar[e][2 * j]     : 0u;
                            uint32_t v1 = (lok && (rgbase + 2 * j + 1) < rc) ? ar[e][2 * j + 1] : 0u;
                            PACK2(A2[e][j], v0, v1);
                        }
                }
                const uint64_t* nqx = (const uint64_t*)(s_qx + colbase);
                const uint64_t* nqy = (const uint64_t*)(s_qy + colbase);
                const uint64_t* nqz = (const uint64_t*)(s_qz + colbase);
#pragma unroll
                for (int tt = 0; tt < 8; tt++) {
                    const int t = tp * 8 + tt;
                    const float* Rt = s_rot + t * 12;
                    float px = fmaf(Rt[0], xl, fmaf(Rt[1], yl, fmaf(Rt[2], zl, Rt[9])));
                    float py = fmaf(Rt[3], xl, fmaf(Rt[4], yl, fmaf(Rt[5], zl, Rt[10])));
                    float pz = fmaf(Rt[6], xl, fmaf(Rt[7], yl, fmaf(Rt[8], zl, Rt[11])));
                    uint64_t px2, py2, pz2;
                    PACK2(px2, __float_as_uint(px), __float_as_uint(px));
                    PACK2(py2, __float_as_uint(py), __float_as_uint(py));
                    PACK2(pz2, __float_as_uint(pz), __float_as_uint(pz));
                    uint64_t a = acc2[tt];
#pragma unroll
                    for (int j = 0; j < 4; j++) {
                        uint64_t dx, dy, dz, d2, t1, t2;
                        ADD2(dx, px2, nqx[j]);
                        ADD2(dy, py2, nqy[j]);
                        ADD2(dz, pz2, nqz[j]);
                        FMA2(t1, dz, dz, eps2);
                        FMA2(t2, dy, dy, t1);
                        FMA2(d2, dx, dx, t2);
                        uint32_t lo, hi;
                        UNPACK2(lo, hi, d2);
                        float ia = rsqrtf(__uint_as_float(lo));
                        float ib = rsqrtf(__uint_as_float(hi));
                        uint64_t inv, inv2, inv3, dd;
                        PACK2(inv, __float_as_uint(ia), __float_as_uint(ib));
                        MUL2(inv2, inv, inv);
                        MUL2(inv3, inv2, inv);
                        MUL2(dd, d2, inv);
                        FMA2(a, A2[0][j], inv3, a);
                        FMA2(a, A2[1][j], inv2, a);
                        FMA2(a, A2[2][j], inv, a);
                        FMA2(a, A2[3][j], dd, a);
                        FMA2(a, A2[4][j], d2, a);
                    }
                    acc2[tt] = a;
                }
            }
#pragma unroll
            for (int tt = 0; tt < 8; tt++) {
                uint32_t lo, hi;
                UNPACK2(lo, hi, acc2[tt]);
                accf[tp * 8 + tt] = __uint_as_float(lo) + __uint_as_float(hi);
            }
        }
        TC_FENCE_BEFORE();
    }
    __syncthreads();
    if (w == 0) TC_DEALLOC(tmem, 512);

#else  // ------------------------- SIMT fallback (non-'a' pass) -------------
    __syncthreads();
    float accf[NT];
#pragma unroll
    for (int t = 0; t < NT; t++) accf[t] = 0.f;
    if (w < 16) {
        const int g = tid >> 3;
        const int j8 = tid & 7;
        const int r = r0 + g;
        const bool rok = r < rc;
        const float qx = rec_coord[((size_t)b * NR + r) * 3 + 0];
        const float qy = rec_coord[((size_t)b * NR + r) * 3 + 1];
        const float qz = rec_coord[((size_t)b * NR + r) * 3 + 2];

        for (int l = 0; l < NL; l++) {
            float dot[NE];
#pragma unroll
            for (int e = 0; e < NE; e++) dot[e] = 0.f;
            if (l < lc && rok) {
                const float* Arow = lig_feat + ((size_t)b * NL + l) * RS;
                const float* Brow = rec_feat + ((size_t)b * NR + r) * RS;
#pragma unroll
                for (int e = 0; e < NE; e++) {
                    float sacc = 0.f;
                    for (int f = j8 * 4; f < NF; f += 32) {
                        float4 av = *(const float4*)(Arow + e * NF + f);
                        float4 bv = *(const float4*)(Brow + e * NF + f);
                        sacc += av.x * bv.x + av.y * bv.y + av.z * bv.z + av.w * bv.w;
                    }
                    dot[e] = sacc;
                }
            }
#pragma unroll
            for (int e = 0; e < NE; e++) {
                dot[e] += __shfl_xor_sync(0xffffffffu, dot[e], 1);
                dot[e] += __shfl_xor_sync(0xffffffffu, dot[e], 2);
                dot[e] += __shfl_xor_sync(0xffffffffu, dot[e], 4);
            }
            float xl = lig_coord[((size_t)b * NL + l) * 3 + 0];
            float yl = lig_coord[((size_t)b * NL + l) * 3 + 1];
            float zl = lig_coord[((size_t)b * NL + l) * 3 + 2];
            for (int t = j8; t < NT; t += 8) {
                const float* Rt = s_rot + t * 12;
                float px = fmaf(Rt[0], xl, fmaf(Rt[1], yl, fmaf(Rt[2], zl, Rt[9])));
                float py = fmaf(Rt[3], xl, fmaf(Rt[4], yl, fmaf(Rt[5], zl, Rt[10])));
                float pz = fmaf(Rt[6], xl, fmaf(Rt[7], yl, fmaf(Rt[8], zl, Rt[11])));
                float dx = px - qx, dy = py - qy, dz = pz - qz;
                float d2 = fmaf(dx, dx, fmaf(dy, dy, dz * dz));
                d2 = fmaxf(d2, 1e-12f);
                float inv = rsqrtf(d2);
                float inv2 = inv * inv;
                float inv3 = inv2 * inv;
                float d = d2 * inv;
                accf[t] += fmaf(dot[0], inv3, fmaf(dot[1], inv2,
                              fmaf(dot[2], inv, fmaf(dot[3], d, dot[4] * d2))));
            }
        }
    }
#endif

    // ---- common block reduction -> g_part[b][rtile][t] (warps 0..15)
    if (w < 16) {
#pragma unroll
        for (int t = 0; t < NT; t++) {
#pragma unroll
            for (int off = 16; off > 0; off >>= 1)
                accf[t] += __shfl_xor_sync(0xffffffffu, accf[t], off);
        }
        if (lane == 0) {
#pragma unroll
            for (int t = 0; t < NT; t++) s_red[w * NT + t] = accf[t];
        }
    }
    __syncthreads();
    if (tid < NT) {
        float s = 0.f;
#pragma unroll
        for (int ww = 0; ww < 16; ww++) s += s_red[ww * NT + tid];
        __stcg(&g_part[(b * 16 + rtile) * NT + tid], s);
    }
    __threadfence();
    __syncthreads();

    if (tid == 0) {
        unsigned old = atomicAdd(&g_ctr, 1u);
        *s_last = ((old & 127u) == 127u) ? 1 : 0;   // grid = 128 CTAs
    }
    __syncthreads();
    if (*s_last) {
        __threadfence();
        if (tid < NB * NT) {
            int bb = tid >> 4, t = tid & 15;
            float ssum = 0.f;
#pragma unroll
            for (int rt = 0; rt < 16; rt++)
                ssum += __ldcg(&g_part[(bb * 16 + rt) * NT + t]);
            out[bb * NT + t] = ssum;
        }
    }
}

// ---------------------------------------------------------------------------
extern "C" void kernel_launch(void* const* d_in, const int* in_sizes, int n_in,
                              void* d_out, int out_size) {
    (void)in_sizes; (void)n_in; (void)out_size;
    const float* lig_feat   = (const float*)d_in[0];
    const float* rec_feat   = (const float*)d_in[1];
    const float* lig_coord  = (const float*)d_in[2];
    const float* rec_coord  = (const float*)d_in[3];
    const float* pre_rot    = (const float*)d_in[4];
    const float* trans      = (const float*)d_in[5];
    const int*   lig_counts = (const int*)d_in[6];
    const int*   rec_counts = (const int*)d_in[7];
    float* out = (float*)d_out;

    cudaFuncSetAttribute(fused_energy, cudaFuncAttributeMaxDynamicSharedMemorySize, FUSED_SMEM);

    dim3 g1(16, NB);
    fused_energy<<<g1, NTHR, FUSED_SMEM>>>(lig_feat, rec_feat, lig_coord, rec_coord,
                                           pre_rot, trans, lig_counts, rec_counts, out);
}

// round 16
// speedup vs baseline: 1.2766x; 1.2024x over previous
#include <cuda_runtime.h>
#include <cuda_bf16.h>
#include <math.h>
#include <stdint.h>

#define NB 8
#define NT 16
#define NL 128
#define NR 1024
#define NE 5
#define NF 512
#define RS (NE * NF)      // 2560

#define BRN 64            // r-tile per CTA (MMA N)
#define BKF 64            // fp32 K per chunk
#define NITER (NE * (NF / BKF))   // 40
#define NSTAGE 3
#define NTHR 512

#if defined(__CUDA_ARCH__) && (defined(__CUDA_ARCH_FEAT_SM103_ALL) || defined(__CUDA_ARCH_FEAT_SM100_ALL))
#define HAS_TC 1
#else
#define HAS_TC 0
#endif

__device__ float g_part[NB * 16 * NT];   // [b][rtile][t]
__device__ unsigned int g_ctr;

// ---------------------------------------------------------------- helpers
__device__ __forceinline__ uint32_t smem_u32(const void* p) {
    uint32_t a;
    asm("{ .reg .u64 t; cvta.to.shared.u64 t, %1; cvt.u32.u64 %0, t; }" : "=r"(a) : "l"(p));
    return a;
}
__device__ __forceinline__ uint32_t packbf2(__nv_bfloat162 v) {
    return *reinterpret_cast<uint32_t*>(&v);
}

#if HAS_TC
#define MBAR_INIT(a, n) asm volatile("mbarrier.init.shared.b64 [%0], %1;" :: "r"(a), "r"(n) : "memory")
#define MBAR_WAIT(a, ph) do {                                                     \
    uint32_t _m = (a), _p = (ph), _d;                                             \
    asm volatile("{\n\t.reg .pred p;\n\t"                                         \
        "mbarrier.try_wait.parity.acquire.cta.shared::cta.b64 p, [%1], %2;\n\t"   \
        "selp.b32 %0, 1, 0, p;\n\t}" : "=r"(_d) : "r"(_m), "r"(_p) : "memory");   \
    if (!_d) {                                                                    \
        asm volatile("{\n\t.reg .pred P1;\n\tW%=:\n\t"                            \
            "mbarrier.try_wait.parity.acquire.cta.shared::cta.b64 P1, [%0], %1, 0x989680;\n\t" \
            "@P1 bra.uni D%=;\n\tbra.uni W%=;\n\tD%=:\n\t}"                       \
            :: "r"(_m), "r"(_p) : "memory");                                      \
    }                                                                             \
} while (0)
#define FENCE_ASYNC_SHARED() asm volatile("fence.proxy.async.shared::cta;" ::: "memory")
#define TC_ALLOC(sm_, n)  asm volatile("tcgen05.alloc.cta_group::1.sync.aligned.shared::cta.b32 [%0], %1;" :: "r"(sm_), "r"(n) : "memory")
#define TC_DEALLOC(t, n)  asm volatile("tcgen05.dealloc.cta_group::1.sync.aligned.b32 %0, %1;" :: "r"(t), "r"(n))
#define TC_RELINQ()       asm volatile("tcgen05.relinquish_alloc_permit.cta_group::1.sync.aligned;")
#define TC_COMMIT(mb)     asm volatile("tcgen05.commit.cta_group::1.mbarrier::arrive::one.shared::cluster.b64 [%0];" :: "r"(mb) : "memory")
#define TC_FENCE_AFTER()  asm volatile("tcgen05.fence::after_thread_sync;" ::: "memory")
#define TC_FENCE_BEFORE() asm volatile("tcgen05.fence::before_thread_sync;" ::: "memory")
#define TC_WAIT_LD()      asm volatile("tcgen05.wait::ld.sync.aligned;" ::: "memory")

#define TC_LD_X8(r, ta) \
    asm volatile("tcgen05.ld.sync.aligned.32x32b.x8.b32 " \
        "{%0,%1,%2,%3,%4,%5,%6,%7}, [%8];" \
        : "=r"((r)[0]),"=r"((r)[1]),"=r"((r)[2]),"=r"((r)[3]), \
          "=r"((r)[4]),"=r"((r)[5]),"=r"((r)[6]),"=r"((r)[7]) \
        : "r"(ta))

__device__ __forceinline__ uint64_t make_desc(uint32_t addr) {
    const uint64_t base =
        (uint64_t(2) << 61) | (uint64_t(1) << 46) | (uint64_t(64) << 32) | (uint64_t(1) << 16);
    return base | ((uint64_t)(addr >> 4) & 0x3FFF);
}
__device__ __forceinline__ void mma_bf16_ss(uint32_t d, uint64_t ad, uint64_t bd,
                                            uint32_t idesc, uint32_t en) {
    asm volatile("{\n\t.reg .pred p;\n\tsetp.ne.u32 p, %4, 0;\n\t"
        "tcgen05.mma.cta_group::1.kind::f16 [%0], %1, %2, %3, {%5,%5,%5,%5}, p;\n\t}"
        :: "r"(d), "l"(ad), "l"(bd), "r"(idesc), "r"(en), "r"(0u) : "memory");
}
#define FMA2(d, a, b, c) asm("fma.rn.f32x2 %0, %1, %2, %3;" : "=l"(d) : "l"(a), "l"(b), "l"(c))
#define ADD2(d, a, b)    asm("add.rn.f32x2 %0, %1, %2;"     : "=l"(d) : "l"(a), "l"(b))
#define MUL2(d, a, b)    asm("mul.rn.f32x2 %0, %1, %2;"     : "=l"(d) : "l"(a), "l"(b))
#define PACK2(d, lo, hi)  asm("mov.b64 %0, {%1, %2};" : "=l"(d) : "r"(lo), "r"(hi))
#define UNPACK2(lo, hi, s) asm("mov.b64 {%0, %1}, %2;" : "=r"(lo), "=r"(hi) : "l"(s))
#endif  // HAS_TC

#define IDESC ((1u << 4) | (1u << 7) | (1u << 10) | ((BRN / 8) << 17) | ((128 / 16) << 24))

// SMEM layout — relative to in-kernel 1024-aligned base.
#define SM_TMEMP 0
#define SM_EMPTYB 48         // 3 x 8B (empty barriers only)
#define SM_DONE 80
#define SM_LAST 96
#define SROT_OFF 128
#define SQ_OFF 896
#define RED_OFF 1664
#define STAGE0 3072
#define STAGE_BYTES 49152
#define AHI_OFF(s) (STAGE0 + (s) * STAGE_BYTES)
#define ALO_OFF(s) (AHI_OFF(s) + 16384)
#define BHI_OFF(s) (AHI_OFF(s) + 32768)
#define BLO_OFF(s) (AHI_OFF(s) + 40960)
#define FUSED_SMEM (STAGE0 + NSTAGE * STAGE_BYTES + 1024)

__device__ __forceinline__ uint32_t swz(uint32_t off) { return off ^ ((off >> 3) & 0x70); }

// ---------------------------------------------------------------------------
// Fused kernel. grid = (16 rtiles, 8 b), 512 threads (16 warps).
// ---------------------------------------------------------------------------
__global__ void __launch_bounds__(NTHR, 1) fused_energy(
    const float* __restrict__ lig_feat,
    const float* __restrict__ rec_feat,
    const float* __restrict__ lig_coord,
    const float* __restrict__ rec_coord,
    const float* __restrict__ pre_rot,
    const float* __restrict__ trans,
    const int* __restrict__ ligc,
    const int* __restrict__ recc,
    float* __restrict__ out) {
    extern __shared__ char smraw[];
    const uint32_t sbraw = smem_u32(smraw);
    const uint32_t sb = (sbraw + 1023u) & ~1023u;
    char* sm = smraw + (sb - sbraw);

    const int tid = threadIdx.x;
    const int b = blockIdx.y;
    const int rtile = blockIdx.x;
    const int r0 = rtile * BRN;

    float* s_rot = (float*)(sm + SROT_OFF);
    float* s_qx = (float*)(sm + SQ_OFF);
    float* s_qy = s_qx + 64;
    float* s_qz = s_qx + 128;
    float* s_red = (float*)(sm + RED_OFF);
    volatile int* s_last = (volatile int*)(sm + SM_LAST);

    // ---- Phase 0: QR (LAPACK convention) + neg rec coords
    if (tid < NT) {
        const int t = tid;
        const float* A0 = pre_rot + (b * NT + t) * 9;
        float a00 = A0[0], a01 = A0[1], a02 = A0[2];
        float a10 = A0[3], a11 = A0[4], a12 = A0[5];
        float a20 = A0[6], a21 = A0[7], a22 = A0[8];
        float v1 = 0.f, v2 = 0.f, tau0 = 0.f;
        float xn2 = a10 * a10 + a20 * a20;
        if (xn2 > 0.f) {
            float beta = -copysignf(sqrtf(a00 * a00 + xn2), a00);
            tau0 = (beta - a00) / beta;
            float inv = 1.f / (a00 - beta);
            v1 = a10 * inv; v2 = a20 * inv;
            float w1 = a01 + v1 * a11 + v2 * a21;
            a01 -= tau0 * w1; a11 -= tau0 * v1 * w1; a21 -= tau0 * v2 * w1;
            float w2 = a02 + v1 * a12 + v2 * a22;
            a02 -= tau0 * w2; a12 -= tau0 * v1 * w2; a22 -= tau0 * v2 * w2;
        }
        float u2 = 0.f, tau1 = 0.f;
        if (a21 != 0.f) {
            float beta1 = -copysignf(sqrtf(a11 * a11 + a21 * a21), a11);
            tau1 = (beta1 - a11) / beta1;
            u2 = a21 / (a11 - beta1);
        }
        float H0m[3][3] = {
            {1.f - tau0, -tau0 * v1, -tau0 * v2},
            {-tau0 * v1, 1.f - tau0 * v1 * v1, -tau0 * v1 * v2},
            {-tau0 * v2, -tau0 * v1 * v2, 1.f - tau0 * v2 * v2}};
        float H1m[3][3] = {
            {1.f, 0.f, 0.f},
            {0.f, 1.f - tau1, -tau1 * u2},
            {0.f, -tau1 * u2, 1.f - tau1 * u2 * u2}};
#pragma unroll
        for (int i = 0; i < 3; i++)
#pragma unroll
            for (int jj = 0; jj < 3; jj++)
                s_rot[t * 12 + i * 3 + jj] =
                    H0m[i][0] * H1m[0][jj] + H0m[i][1] * H1m[1][jj] + H0m[i][2] * H1m[2][jj];
        s_rot[t * 12 + 9]  = trans[(b * NT + t) * 3 + 0];
        s_rot[t * 12 + 10] = trans[(b * NT + t) * 3 + 1];
        s_rot[t * 12 + 11] = trans[(b * NT + t) * 3 + 2];
    }
    if (tid >= 64 && tid < 128) {
        int r = r0 + (tid - 64);
        s_qx[tid - 64] = -rec_coord[((size_t)b * NR + r) * 3 + 0];
        s_qy[tid - 64] = -rec_coord[((size_t)b * NR + r) * 3 + 1];
        s_qz[tid - 64] = -rec_coord[((size_t)b * NR + r) * 3 + 2];
    }

    const int lc = __ldg(&ligc[b]);
    const int rc = __ldg(&recc[b]);
    const int lane = tid & 31;
    const int w = tid >> 5;

#if HAS_TC
    if (tid == 0) {
#pragma unroll
        for (int s = 0; s < NSTAGE; s++) MBAR_INIT(sb + SM_EMPTYB + 8 * s, 1);
        MBAR_INIT(sb + SM_DONE, 1);
    }
    if (w == 0) {
        TC_ALLOC(sb + SM_TMEMP, 512);
        TC_RELINQ();
    }
    __syncthreads();
    uint32_t tmem;
    asm volatile("ld.shared.b32 %0, [%1];" : "=r"(tmem) : "r"(sb + SM_TMEMP));

    const float* Abase = lig_feat + (size_t)b * NL * RS;
    const float* Bbase = rec_feat + ((size_t)b * NR + r0) * RS;

    // per-thread invariant offsets: rows (tid>>4)+32i, col (tid&15)
    size_t aoff[4];
    uint32_t soA[4];
#pragma unroll
    for (int i = 0; i < 4; i++) {
        int row = (tid >> 4) + 32 * i;
        aoff[i] = (size_t)row * RS + ((tid & 15) << 2);
        soA[i] = swz((uint32_t)row * 128 + ((tid & 15) << 3));
    }

    float4 pa0[4], pb0[2], pa1[4], pb1[2];
    {
#pragma unroll
        for (int i = 0; i < 4; i++) pa0[i] = *(const float4*)(Abase + aoff[i]);
#pragma unroll
        for (int i = 0; i < 2; i++) pb0[i] = *(const float4*)(Bbase + aoff[i]);
    }

#define CVT_PAIR(V, HDST, LDST, SO)                                               \
    do {                                                                          \
        float4 v = (V);                                                           \
        __nv_bfloat162 h01 = __floats2bfloat162_rn(v.x, v.y);                     \
        __nv_bfloat162 h23 = __floats2bfloat162_rn(v.z, v.w);                     \
        float2 f01 = __bfloat1622float2(h01);                                     \
        float2 f23 = __bfloat1622float2(h23);                                     \
        __nv_bfloat162 l01 = __floats2bfloat162_rn(v.x - f01.x, v.y - f01.y);     \
        __nv_bfloat162 l23 = __floats2bfloat162_rn(v.z - f23.x, v.w - f23.y);     \
        *(uint2*)((HDST) + (SO)) = make_uint2(packbf2(h01), packbf2(h23));        \
        *(uint2*)((LDST) + (SO)) = make_uint2(packbf2(l01), packbf2(l23));        \
    } while (0)

// per-iter protocol: empty-wait -> cvt+STS -> __syncthreads -> tid0: fence+MMA+commit
#define STEP(ITER, CA, CB, NA, NB_)                                               \
    {                                                                             \
        const int iter_ = (ITER);                                                 \
        if (iter_ + 1 < NITER) {                                                  \
            const int nx = iter_ + 1;                                             \
            const float* An = Abase + (nx >> 3) * NF + (nx & 7) * BKF;            \
            const float* Bn = Bbase + (nx >> 3) * NF + (nx & 7) * BKF;            \
            _Pragma("unroll")                                                     \
            for (int i = 0; i < 4; i++) NA[i] = *(const float4*)(An + aoff[i]);   \
            _Pragma("unroll")                                                     \
            for (int i = 0; i < 2; i++) NB_[i] = *(const float4*)(Bn + aoff[i]);  \
        }                                                                         \
        const int k_ = iter_ / 3;                                                 \
        const int s_ = iter_ - 3 * k_;                                            \
        MBAR_WAIT(sb + SM_EMPTYB + 8 * s_, (k_ & 1) ^ 1);                         \
        char* ah_ = sm + AHI_OFF(s_);                                             \
        char* al_ = sm + ALO_OFF(s_);                                             \
        _Pragma("unroll")                                                         \
        for (int i = 0; i < 4; i++) CVT_PAIR(CA[i], ah_, al_, soA[i]);            \
        char* bh_ = sm + BHI_OFF(s_);                                             \
        char* bl_ = sm + BLO_OFF(s_);                                             \
        _Pragma("unroll")                                                         \
        for (int i = 0; i < 2; i++) CVT_PAIR(CB[i], bh_, bl_, soA[i]);            \
        __syncthreads();                                                          \
        if (tid == 0) {                                                           \
            FENCE_ASYNC_SHARED();                                                 \
            uint64_t dah = make_desc(sb + AHI_OFF(s_));                           \
            uint64_t dal = make_desc(sb + ALO_OFF(s_));                           \
            uint64_t dbh = make_desc(sb + BHI_OFF(s_));                           \
            uint64_t dbl = make_desc(sb + BLO_OFF(s_));                           \
            uint32_t dcol = tmem + (iter_ >> 3) * 64;                             \
            const int kc_ = iter_ & 7;                                            \
            _Pragma("unroll")                                                     \
            for (int ks = 0; ks < 4; ks++) {                                      \
                uint64_t o = ks * 2;                                              \
                mma_bf16_ss(dcol, dah + o, dbh + o, IDESC, !(kc_ == 0 && ks == 0)); \
                mma_bf16_ss(dcol, dah + o, dbl + o, IDESC, 1u);                   \
                mma_bf16_ss(dcol, dal + o, dbh + o, IDESC, 1u);                   \
            }                                                                     \
            TC_COMMIT(sb + SM_EMPTYB + 8 * s_);                                   \
        }                                                                         \
    }

    for (int it2 = 0; it2 < NITER; it2 += 2) {
        STEP(it2, pa0, pb0, pa1, pb1);
        STEP(it2 + 1, pa1, pb1, pa0, pb0);
    }
#undef STEP
#undef CVT_PAIR

    if (tid == 0) TC_COMMIT(sb + SM_DONE);
    MBAR_WAIT(sb + SM_DONE, 0);
    TC_FENCE_AFTER();

    // ---- Phase 2: epilogue. warp w: rows (w&3)*32+lane, cols (w>>2)*16..+15.
    const int l = (w & 3) * 32 + lane;
    const int colq = w >> 2;     // 0..3
    const bool lok = l < lc;
    const float xl = lig_coord[((size_t)b * NL + l) * 3 + 0];
    const float yl = lig_coord[((size_t)b * NL + l) * 3 + 1];
    const float zl = lig_coord[((size_t)b * NL + l) * 3 + 2];

    float accf[NT];
    uint64_t eps2;
    PACK2(eps2, __float_as_uint(1e-12f), __float_as_uint(1e-12f));

#pragma unroll
    for (int tp = 0; tp < 2; tp++) {        // two t-passes of 8
        uint64_t acc2[8];
#pragma unroll
        for (int t = 0; t < 8; t++) acc2[t] = 0ull;
#pragma unroll
        for (int cchunk = 0; cchunk < 2; cchunk++) {
            const int colbase = colq * 16 + cchunk * 8;
            uint64_t A2[NE][4];
            {
                uint32_t ar[NE][8];
#pragma unroll
                for (int e = 0; e < NE; e++)
                    TC_LD_X8(ar[e], tmem + e * 64 + colbase);
                TC_WAIT_LD();     // single wait for all 5 loads
                const int rgbase = r0 + colbase;
#pragma unroll
                for (int e = 0; e < NE; e++)
#pragma unroll
                    for (int j = 0; j < 4; j++) {
                        uint32_t v0 = (lok && (rgbase + 2 * j)     < rc) ? ar[e][2 * j]     : 0u;
                        uint32_t v1 = (lok && (rgbase + 2 * j + 1) < rc) ? ar[e][2 * j + 1] : 0u;
                        PACK2(A2[e][j], v0, v1);
                    }
            }
            const uint64_t* nqx = (const uint64_t*)(s_qx + colbase);
            const uint64_t* nqy = (const uint64_t*)(s_qy + colbase);
            const uint64_t* nqz = (const uint64_t*)(s_qz + colbase);
#pragma unroll
            for (int tt = 0; tt < 8; tt++) {
                const int t = tp * 8 + tt;
                const float* Rt = s_rot + t * 12;
                float px = fmaf(Rt[0], xl, fmaf(Rt[1], yl, fmaf(Rt[2], zl, Rt[9])));
                float py = fmaf(Rt[3], xl, fmaf(Rt[4], yl, fmaf(Rt[5], zl, Rt[10])));
                float pz = fmaf(Rt[6], xl, fmaf(Rt[7], yl, fmaf(Rt[8], zl, Rt[11])));
                uint64_t px2, py2, pz2;
                PACK2(px2, __float_as_uint(px), __float_as_uint(px));
                PACK2(py2, __float_as_uint(py), __float_as_uint(py));
                PACK2(pz2, __float_as_uint(pz), __float_as_uint(pz));
                uint64_t a = acc2[tt];
#pragma unroll
                for (int j = 0; j < 4; j++) {
                    uint64_t dx, dy, dz, d2, t1, t2;
                    ADD2(dx, px2, nqx[j]);
                    ADD2(dy, py2, nqy[j]);
                    ADD2(dz, pz2, nqz[j]);
                    FMA2(t1, dz, dz, eps2);
                    FMA2(t2, dy, dy, t1);
                    FMA2(d2, dx, dx, t2);
                    uint32_t lo, hi;
                    UNPACK2(lo, hi, d2);
                    float ia = rsqrtf(__uint_as_float(lo));
                    float ib = rsqrtf(__uint_as_float(hi));
                    uint64_t inv, inv2, inv3, dd;
                    PACK2(inv, __float_as_uint(ia), __float_as_uint(ib));
                    MUL2(inv2, inv, inv);
                    MUL2(inv3, inv2, inv);
                    MUL2(dd, d2, inv);
                    FMA2(a, A2[0][j], inv3, a);
                    FMA2(a, A2[1][j], inv2, a);
                    FMA2(a, A2[2][j], inv, a);
                    FMA2(a, A2[3][j], dd, a);
                    FMA2(a, A2[4][j], d2, a);
                }
                acc2[tt] = a;
            }
        }
#pragma unroll
        for (int tt = 0; tt < 8; tt++) {
            uint32_t lo, hi;
            UNPACK2(lo, hi, acc2[tt]);
            accf[tp * 8 + tt] = __uint_as_float(lo) + __uint_as_float(hi);
        }
    }
    TC_FENCE_BEFORE();
    __syncthreads();
    if (w == 0) TC_DEALLOC(tmem, 512);

#else  // ------------------------- SIMT fallback (non-'a' pass) -------------
    __syncthreads();
    const int g = tid >> 3;
    const int j8 = tid & 7;
    const int r = r0 + g;
    const bool rok = r < rc;
    const float qx = rec_coord[((size_t)b * NR + r) * 3 + 0];
    const float qy = rec_coord[((size_t)b * NR + r) * 3 + 1];
    const float qz = rec_coord[((size_t)b * NR + r) * 3 + 2];
    float accf[NT];
#pragma unroll
    for (int t = 0; t < NT; t++) accf[t] = 0.f;

    for (int l = 0; l < NL; l++) {
        float dot[NE];
#pragma unroll
        for (int e = 0; e < NE; e++) dot[e] = 0.f;
        if (l < lc && rok) {
            const float* Arow = lig_feat + ((size_t)b * NL + l) * RS;
            const float* Brow = rec_feat + ((size_t)b * NR + r) * RS;
#pragma unroll
            for (int e = 0; e < NE; e++) {
                float sacc = 0.f;
                for (int f = j8 * 4; f < NF; f += 32) {
                    float4 av = *(const float4*)(Arow + e * NF + f);
                    float4 bv = *(const float4*)(Brow + e * NF + f);
                    sacc += av.x * bv.x + av.y * bv.y + av.z * bv.z + av.w * bv.w;
                }
                dot[e] = sacc;
            }
        }
#pragma unroll
        for (int e = 0; e < NE; e++) {
            dot[e] += __shfl_xor_sync(0xffffffffu, dot[e], 1);
            dot[e] += __shfl_xor_sync(0xffffffffu, dot[e], 2);
            dot[e] += __shfl_xor_sync(0xffffffffu, dot[e], 4);
        }
        float xl = lig_coord[((size_t)b * NL + l) * 3 + 0];
        float yl = lig_coord[((size_t)b * NL + l) * 3 + 1];
        float zl = lig_coord[((size_t)b * NL + l) * 3 + 2];
        for (int t = j8; t < NT; t += 8) {
            const float* Rt = s_rot + t * 12;
            float px = fmaf(Rt[0], xl, fmaf(Rt[1], yl, fmaf(Rt[2], zl, Rt[9])));
            float py = fmaf(Rt[3], xl, fmaf(Rt[4], yl, fmaf(Rt[5], zl, Rt[10])));
            float pz = fmaf(Rt[6], xl, fmaf(Rt[7], yl, fmaf(Rt[8], zl, Rt[11])));
            float dx = px - qx, dy = py - qy, dz = pz - qz;
            float d2 = fmaf(dx, dx, fmaf(dy, dy, dz * dz));
            d2 = fmaxf(d2, 1e-12f);
            float inv = rsqrtf(d2);
            float inv2 = inv * inv;
            float inv3 = inv2 * inv;
            float d = d2 * inv;
            accf[t] += fmaf(dot[0], inv3, fmaf(dot[1], inv2,
                          fmaf(dot[2], inv, fmaf(dot[3], d, dot[4] * d2))));
        }
    }
#endif

    // ---- common block reduction -> g_part[b][rtile][t]
#pragma unroll
    for (int t = 0; t < NT; t++) {
#pragma unroll
        for (int off = 16; off > 0; off >>= 1)
            accf[t] += __shfl_xor_sync(0xffffffffu, accf[t], off);
    }
    if (lane == 0) {
#pragma unroll
        for (int t = 0; t < NT; t++) s_red[w * NT + t] = accf[t];
    }
    __syncthreads();
    if (tid < NT) {
        float s = 0.f;
#pragma unroll
        for (int ww = 0; ww < 16; ww++) s += s_red[ww * NT + tid];
        __stcg(&g_part[(b * 16 + rtile) * NT + tid], s);
    }
    __threadfence();
    __syncthreads();

    if (tid == 0) {
        unsigned old = atomicAdd(&g_ctr, 1u);
        *s_last = ((old & 127u) == 127u) ? 1 : 0;   // grid = 128 CTAs
    }
    __syncthreads();
    if (*s_last) {
        __threadfence();
        if (tid < NB * NT) {
            int bb = tid >> 4, t = tid & 15;
            float ssum = 0.f;
#pragma unroll
            for (int rt = 0; rt < 16; rt++)
                ssum += __ldcg(&g_part[(bb * 16 + rt) * NT + t]);
            out[bb * NT + t] = ssum;
        }
    }
}

// ---------------------------------------------------------------------------
extern "C" void kernel_launch(void* const* d_in, const int* in_sizes, int n_in,
                              void* d_out, int out_size) {
    (void)in_sizes; (void)n_in; (void)out_size;
    const float* lig_feat   = (const float*)d_in[0];
    const float* rec_feat   = (const float*)d_in[1];
    const float* lig_coord  = (const float*)d_in[2];
    const float* rec_coord  = (const float*)d_in[3];
    const float* pre_rot    = (const float*)d_in[4];
    const float* trans      = (const float*)d_in[5];
    const int*   lig_counts = (const int*)d_in[6];
    const int*   rec_counts = (const int*)d_in[7];
    float* out = (float*)d_out;

    cudaFuncSetAttribute(fused_energy, cudaFuncAttributeMaxDynamicSharedMemorySize, FUSED_SMEM);

    dim3 g1(16, NB);
    fused_energy<<<g1, NTHR, FUSED_SMEM>>>(lig_feat, rec_feat, lig_coord, rec_coord,
                                           pre_rot, trans, lig_counts, rec_counts, out);
}